// round 17
// baseline (speedup 1.0000x reference)
#include <cuda_runtime.h>
#include <cuda.h>
#include <cstdint>

// AlignedLinear: y[n, o*9+d] = alpha * sum_i x[n, i*9+d] * K[r(d), i, o]
// r(d)=0 d=0; 1 d=1..3; 2 d=4..8.
//
// R17: R16 structure (MT=8, d-paired m16 fragments, 6 CTAs/SM) with the
// issue-count fat removed:
//  - B regrouped [r][k8][wg][lane][4nt]: each thread's 4 nt fragments are 32
//    contiguous bytes -> 2x LDG.128 per k8 (was 4x LDG.64), warp-coalesced,
//    addresses fold to [reg+IMM] under full unroll.
//  - k8 loop FULLY unrolled: all swizzle math constant-folds to ~2 ops/addr.
// Pairs (d1,d2),(d4,d5),(d6,d7); halves d0,d3,d8 (a1:=a0, hi discarded).
// Tile 36864 B -> 6 CTAs/SM x 4 warps (occ 37.5%). TMA in/out (SW128, view
// [32f][node][36seg], chunk=8seg+node -> key=node&7 per-lane CONSTANT).

#define MT        8
#define DIMT      9
#define MUL       128
#define ROWF      1152
#define TILE_BYTES (MT * ROWF * 4)      // 36864
#define SEG_STRIDE (MT * 128)           // 1024 B per seg in smem
#define NTHREADS  128
#define ALPHA_F   0.08838834764831845f  // sqrt(1/128)

// kbuf[r][k8][wg][lane][nt4][j]: thread (wg,lane)'s 4 nt fragments, 32B.
#define KB_WORDS  (3 * 16 * 4 * 32 * 8)
__device__ __align__(16) uint32_t g_kbuf[KB_WORDS];

static __device__ __forceinline__ uint32_t f2tf32(float f) {
    uint32_t u;
    asm("cvt.rna.tf32.f32 %0, %1;" : "=r"(u) : "f"(f));
    return u;
}

static __device__ __forceinline__ void mma_tf32(float c[4],
    uint32_t a0, uint32_t a1, uint32_t a2, uint32_t a3,
    uint32_t b0, uint32_t b1)
{
    asm volatile(
        "mma.sync.aligned.m16n8k8.row.col.f32.tf32.tf32.f32 "
        "{%0,%1,%2,%3}, {%4,%5,%6,%7}, {%8,%9}, {%0,%1,%2,%3};"
        : "+f"(c[0]), "+f"(c[1]), "+f"(c[2]), "+f"(c[3])
        : "r"(a0), "r"(a1), "r"(a2), "r"(a3), "r"(b0), "r"(b1));
}

// ---- Prep: K[r][i][o] fp32 -> regrouped fragment-major tf32, alpha folded --
__global__ void prep_k_kernel(const float* __restrict__ kern)
{
    int idx = blockIdx.x * blockDim.x + threadIdx.x;
    if (idx >= KB_WORDS) return;
    int j    = idx & 1;
    int ntin = (idx >> 1) & 3;
    int lane = (idx >> 3) & 31;
    int wg   = (idx >> 8) & 3;
    int k8   = (idx >> 10) & 15;
    int r    = idx >> 14;
    int nt = wg * 4 + ntin;
    int k  = k8 * 8 + (lane & 3) + 4 * j;
    int o  = nt * 8 + (lane >> 2);
    g_kbuf[idx] = f2tf32(ALPHA_F * kern[(r * MUL + k) * MUL + o]);
}

// Swizzled byte offset (relative to node-row base) of word w = 9k+d.
// chunk = seg*8 + node -> key = (node&7)<<4 = xm, per-lane constant.
static __device__ __forceinline__ uint32_t swz(int w, uint32_t xm) {
    return ((uint32_t)w >> 5) * (uint32_t)SEG_STRIDE
         + ((((uint32_t)w & 31u) << 2) ^ xm);
}

static __device__ __forceinline__ uint32_t lds32(uint32_t a) {
    uint32_t v;
    asm volatile("ld.shared.b32 %0, [%1];" : "=r"(v) : "r"(a));
    return v;
}
static __device__ __forceinline__ void sts32(uint32_t a, float v) {
    asm volatile("st.shared.b32 [%0], %1;" :: "r"(a), "f"(v));
}

static __device__ __forceinline__ void mbar_wait(uint32_t bar, uint32_t parity) {
    asm volatile(
        "{\n\t.reg .pred P;\n\t"
        "WL_%=:\n\t"
        "mbarrier.try_wait.parity.acquire.cta.shared::cta.b64 P, [%0], %1, 0x989680;\n\t"
        "@P bra WD_%=;\n\t"
        "bra WL_%=;\n\t"
        "WD_%=:\n\t}"
        :: "r"(bar), "r"(parity) : "memory");
}

// One pass over K for irrep R with up to two fragments:
//   F0 = (DA0, DB0), F1 = (DA1, DB1); DB=-1 -> half fragment (hi discarded),
//   DA1=-1 -> no second fragment. All fragments share this pass's B.
template<int R, int DA0, int DB0, int DA1, int DB1>
static __device__ __forceinline__ void process_pass(
    uint32_t rowb, uint32_t xm, int tg, int warp)
{
    // uint4 base index for (R, k8=0, warp, lane): per-k8 stride = 256 uint4.
    const uint4* kb4 = reinterpret_cast<const uint4*>(g_kbuf)
                     + ((size_t)(R * 16) * 4 + warp) * 64
                     + (size_t)(threadIdx.x & 31) * 2;
    constexpr int NF = (DA1 >= 0) ? 2 : 1;

    float acc[NF][4][4];
    #pragma unroll
    for (int f = 0; f < NF; ++f)
        #pragma unroll
        for (int nt = 0; nt < 4; ++nt)
            #pragma unroll
            for (int i = 0; i < 4; ++i) acc[f][nt][i] = 0.f;

    uint4 buf[2][2];
    buf[0][0] = __ldg(kb4);           buf[0][1] = __ldg(kb4 + 1);
    buf[1][0] = __ldg(kb4 + 256);     buf[1][1] = __ldg(kb4 + 257);

    #pragma unroll
    for (int k8 = 0; k8 < 16; ++k8) {
        const uint4 b01 = buf[k8 & 1][0];
        const uint4 b23 = buf[k8 & 1][1];
        if (k8 < 14) {
            buf[k8 & 1][0] = __ldg(kb4 + (k8 + 2) * 256);
            buf[k8 & 1][1] = __ldg(kb4 + (k8 + 2) * 256 + 1);
        }
        const int wbase = 72 * k8 + 9 * tg;

        #pragma unroll
        for (int f = 0; f < NF; ++f) {
            const int da = (f == 0) ? DA0 : DA1;
            const int db = (f == 0) ? DB0 : DB1;
            const int wa = wbase + da;
            uint32_t a0 = lds32(rowb + swz(wa,      xm));
            uint32_t a2 = lds32(rowb + swz(wa + 36, xm));
            uint32_t a1 = a0, a3 = a2;
            if (db >= 0) {
                const int wb = wbase + db;
                a1 = lds32(rowb + swz(wb,      xm));
                a3 = lds32(rowb + swz(wb + 36, xm));
            }
            mma_tf32(acc[f][0], a0, a1, a2, a3, b01.x, b01.y);
            mma_tf32(acc[f][1], a0, a1, a2, a3, b01.z, b01.w);
            mma_tf32(acc[f][2], a0, a1, a2, a3, b23.x, b23.y);
            mma_tf32(acc[f][3], a0, a1, a2, a3, b23.z, b23.w);
        }
    }

    __syncthreads();   // all warps done reading this pass's d-words

    // Writeback: rows 0-7 -> (node g, da); rows 8-15 -> (node g, db).
    #pragma unroll
    for (int f = 0; f < NF; ++f) {
        const int da = (f == 0) ? DA0 : DA1;
        const int db = (f == 0) ? DB0 : DB1;
        #pragma unroll
        for (int nt = 0; nt < 4; ++nt) {
            const int o = warp * 32 + nt * 8 + 2 * tg;
            sts32(rowb + swz(o * 9 + da,       xm), acc[f][nt][0]);
            sts32(rowb + swz((o + 1) * 9 + da, xm), acc[f][nt][1]);
            if (db >= 0) {
                sts32(rowb + swz(o * 9 + db,       xm), acc[f][nt][2]);
                sts32(rowb + swz((o + 1) * 9 + db, xm), acc[f][nt][3]);
            }
        }
    }
}

__global__ void __launch_bounds__(NTHREADS, 6)
aligned_linear_pair(const __grid_constant__ CUtensorMap tmx,
                    const __grid_constant__ CUtensorMap tmy)
{
    extern __shared__ uint32_t dyn[];
    const uint32_t raw   = (uint32_t)__cvta_generic_to_shared(dyn);
    const uint32_t tbase = (raw + 1023u) & ~1023u;   // SW128: 1KB align
    const uint32_t bar   = tbase + TILE_BYTES;

    const int tid  = threadIdx.x;
    const int lane = tid & 31;
    const int warp = tid >> 5;
    const int g    = lane >> 2;
    const int tg   = lane & 3;
    const int node0 = blockIdx.x * MT;

    const uint32_t xm   = (uint32_t)g << 4;      // swizzle key, constant
    const uint32_t rowb = tbase + (uint32_t)g * 128u;

    if (tid == 0)
        asm volatile("mbarrier.init.shared.b64 [%0], 1;" :: "r"(bar));
    __syncthreads();

    if (tid == 0) {
        asm volatile("mbarrier.arrive.expect_tx.shared.b64 _, [%0], %1;"
                     :: "r"(bar), "r"(TILE_BYTES));
        asm volatile(
            "cp.async.bulk.tensor.3d.shared::cta.global.tile"
            ".mbarrier::complete_tx::bytes [%0], [%1, {%2, %3, %4}], [%5];"
            :: "r"(tbase), "l"(&tmx),
               "r"(0), "r"(node0), "r"(0), "r"(bar) : "memory");
    }
    mbar_wait(bar, 0u);

    process_pass<0, 0, -1, -1, -1>(rowb, xm, tg, warp);  // d0
    process_pass<1, 1,  2,  3, -1>(rowb, xm, tg, warp);  // (d1,d2),(d3)
    process_pass<2, 4,  5,  6,  7>(rowb, xm, tg, warp);  // (d4,d5),(d6,d7)
    process_pass<2, 8, -1, -1, -1>(rowb, xm, tg, warp);  // d8

    __syncthreads();   // all writebacks visible

    if (tid == 0) {
        asm volatile("fence.proxy.async;" ::: "memory");
        asm volatile(
            "cp.async.bulk.tensor.3d.global.shared::cta.tile.bulk_group "
            "[%0, {%1, %2, %3}], [%4];"
            :: "l"(&tmy), "r"(0), "r"(node0), "r"(0), "r"(tbase) : "memory");
        asm volatile("cp.async.bulk.commit_group;");
        asm volatile("cp.async.bulk.wait_group 0;");
    }
}

extern "C" void kernel_launch(void* const* d_in, const int* in_sizes, int n_in,
                              void* d_out, int out_size)
{
    const float* x = (const float*)d_in[0];
    const float* k = (const float*)d_in[1];
    float* y = (float*)d_out;
    int n_nodes = in_sizes[0] / ROWF;
    int ntiles  = (n_nodes + MT - 1) / MT;

    prep_k_kernel<<<(KB_WORDS + 255) / 256, 256>>>(k);

    typedef CUresult (*enc_t)(CUtensorMap*, CUtensorMapDataType, cuuint32_t,
                              void*, const cuuint64_t*, const cuuint64_t*,
                              const cuuint32_t*, const cuuint32_t*,
                              CUtensorMapInterleave, CUtensorMapSwizzle,
                              CUtensorMapL2promotion, CUtensorMapFloatOOBfill);
    enc_t enc = nullptr;
    {
        void* p = nullptr;
        cudaDriverEntryPointQueryResult qr;
        cudaGetDriverEntryPointByVersion("cuTensorMapEncodeTiled", &p, 12000,
                                         cudaEnableDefault, &qr);
        enc = (enc_t)p;
    }

    // View: [32 floats][node][36 segs]; box [32, 8, 36]; SW128.
    cuuint64_t dims[3]    = {32, (cuuint64_t)n_nodes, 36};
    cuuint64_t strides[2] = {(cuuint64_t)ROWF * 4, 128};
    cuuint32_t box[3]     = {32, MT, 36};
    cuuint32_t es[3]      = {1, 1, 1};

    CUtensorMap tmx, tmy;
    enc(&tmx, CU_TENSOR_MAP_DATA_TYPE_FLOAT32, 3, (void*)x,
        dims, strides, box, es,
        CU_TENSOR_MAP_INTERLEAVE_NONE, CU_TENSOR_MAP_SWIZZLE_128B,
        CU_TENSOR_MAP_L2_PROMOTION_L2_128B, CU_TENSOR_MAP_FLOAT_OOB_FILL_NONE);
    enc(&tmy, CU_TENSOR_MAP_DATA_TYPE_FLOAT32, 3, (void*)y,
        dims, strides, box, es,
        CU_TENSOR_MAP_INTERLEAVE_NONE, CU_TENSOR_MAP_SWIZZLE_128B,
        CU_TENSOR_MAP_L2_PROMOTION_L2_128B, CU_TENSOR_MAP_FLOAT_OOB_FILL_NONE);

    size_t smem = TILE_BYTES + 1024 + 16;   // tile + align slack + mbar
    cudaFuncSetAttribute(aligned_linear_pair,
                         cudaFuncAttributeMaxDynamicSharedMemorySize,
                         (int)smem);

    aligned_linear_pair<<<ntiles, NTHREADS, smem>>>(tmx, tmy);
}